// round 3
// baseline (speedup 1.0000x reference)
#include <cuda_runtime.h>

// ---------------------------------------------------------------------------
// MOE_DISTRIBUTE_CASCADE_GRAPH
//   inv[i]   = stable counting-sort rank of expert_ids.flat[i]   (N = B*K)
//   out[b,h] = sum_k scales[b,k] * G[inv[b*K+k], h]
//   output   = (out, out) concatenated (2*B*H floats)
// ---------------------------------------------------------------------------

#define NBINS   256        // max experts supported (dataset uses 64)
#define RWARPS  32         // warps in the rank block
#define RTHREADS (RWARPS * 32)
#define RREGS   32         // ids preloaded per thread (covers N <= 32768)
#define MAXN    65536      // max B*K supported (dataset uses 32768)

__device__ int g_inv[MAXN];

// --- Kernel 1: fused stable counting-sort rank (single block) ---------------
// Key fix vs R2: every thread PRELOADS its 32 ids into registers up front
// (independent loads, MLP=32), so neither the histogram phase nor the rank
// phase carries a global-load latency in its dependent chain.
__global__ void __launch_bounds__(RTHREADS, 1)
rank_fused_kernel(const int* __restrict__ ids, int n) {
    __shared__ int cnt[RWARPS * NBINS];   // hist -> base -> running counters
    __shared__ int totals[NBINS];
    __shared__ int totals2[NBINS];

    const int tid  = threadIdx.x;
    const int w    = tid >> 5;
    const int lane = tid & 31;
    const int cpw  = (n + RWARPS - 1) / RWARPS;   // elems per warp chunk
    const int beg  = w * cpw;
    const int end  = min(beg + cpw, n);

    // ---- Prefetch: round r's id for this lane = ids[beg + r*32 + lane].
    // All RREGS loads are independent; ptxas front-batches them (one latency).
    int myid[RREGS];
    #pragma unroll
    for (int r = 0; r < RREGS; r++) {
        const int i = beg + r * 32 + lane;
        myid[r] = (i < end) ? ids[i] : -1;
    }

    // zero histograms
    for (int i = tid; i < RWARPS * NBINS; i += RTHREADS) cnt[i] = 0;
    __syncthreads();

    // A) per-warp histogram from registers (+ rare tail beyond RREGS rounds)
    #pragma unroll
    for (int r = 0; r < RREGS; r++)
        if (myid[r] >= 0) atomicAdd(&cnt[w * NBINS + myid[r]], 1);
    for (int i = beg + RREGS * 32 + lane; i < end; i += 32)
        atomicAdd(&cnt[w * NBINS + ids[i]], 1);
    __syncthreads();

    // B1) per-expert exclusive scan over the 32 warp rows (SMEM-only chain)
    if (tid < NBINS) {
        int run = 0;
        #pragma unroll
        for (int ww = 0; ww < RWARPS; ww++) {
            const int h = cnt[ww * NBINS + tid];
            cnt[ww * NBINS + tid] = run;
            run += h;
        }
        totals[tid] = run;
    }
    __syncthreads();

    // B2) inclusive Hillis-Steele scan of expert totals
    #pragma unroll
    for (int d = 1; d < NBINS; d <<= 1) {
        int v = 0;
        if (tid < NBINS) v = (tid >= d) ? totals[tid - d] : 0;
        __syncthreads();
        if (tid < NBINS) totals2[tid] = totals[tid] + v;
        __syncthreads();
        if (tid < NBINS) totals[tid] = totals2[tid];
        __syncthreads();
    }
    // base[e] = exclusive prefix = totals[e-1]
    if (tid < NBINS) {
        const int base = (tid == 0) ? 0 : totals[tid - 1];
        #pragma unroll
        for (int ww = 0; ww < RWARPS; ww++)
            cnt[ww * NBINS + tid] += base;
    }
    __syncthreads();

    // C) stable rank assignment from registers (no global loads in chain)
    int* mycnt = &cnt[w * NBINS];
    #pragma unroll
    for (int r = 0; r < RREGS; r++) {
        const int  id    = myid[r];
        const bool valid = (id >= 0);
        // invalid lanes get unique keys -> singleton groups, no smem touch
        const int key = valid ? id : (NBINS + lane);
        const unsigned mask = __match_any_sync(0xffffffffu, key);
        const int lower  = __popc(mask & ((1u << lane) - 1u));
        const int leader = __ffs(mask) - 1;
        int r0 = 0;
        if (valid && lane == leader) {
            r0 = mycnt[key];
            mycnt[key] = r0 + __popc(mask);
        }
        r0 = __shfl_sync(0xffffffffu, r0, leader);
        if (valid) g_inv[beg + r * 32 + lane] = r0 + lower;
    }
    // rare tail (n > RWARPS*32*RREGS): load in-loop
    for (int i = beg + RREGS * 32 + lane;
         __any_sync(0xffffffffu, i < end); i += 32) {
        const bool valid = (i < end);
        const int key = valid ? ids[i] : (NBINS + lane);
        const unsigned mask = __match_any_sync(0xffffffffu, key);
        const int lower  = __popc(mask & ((1u << lane) - 1u));
        const int leader = __ffs(mask) - 1;
        int r0 = 0;
        if (valid && lane == leader) {
            r0 = mycnt[key];
            mycnt[key] = r0 + __popc(mask);
        }
        r0 = __shfl_sync(0xffffffffu, r0, leader);
        if (valid) g_inv[i] = r0 + lower;
    }
}

// --- Kernel 2: gather-reduce combine (HBM streaming roofline kernel) --------
// R1 form: __ldg gathers, plain stores (measured best: 105.4us, 78.3% DRAM).
__global__ void __launch_bounds__(1024, 1)
combine_kernel(const float* __restrict__ G,
               const float* __restrict__ scales,
               float* __restrict__ out,
               int B, int K, int H4, int dup) {
    const int b = blockIdx.x;
    __shared__ int   rows[16];
    __shared__ float sc[16];
    if (threadIdx.x < (unsigned)K) {
        rows[threadIdx.x] = g_inv[b * K + threadIdx.x];
        sc[threadIdx.x]   = scales[b * K + threadIdx.x];
    }
    __syncthreads();

    const float4* __restrict__ Gv = reinterpret_cast<const float4*>(G);
    float4* __restrict__ ov = reinterpret_cast<float4*>(out);

    for (int h = threadIdx.x; h < H4; h += blockDim.x) {
        float4 acc = make_float4(0.f, 0.f, 0.f, 0.f);
        #pragma unroll 8
        for (int k = 0; k < K; k++) {
            const float  s = sc[k];
            const float4 v = __ldg(&Gv[(size_t)rows[k] * H4 + h]);
            acc.x = fmaf(s, v.x, acc.x);
            acc.y = fmaf(s, v.y, acc.y);
            acc.z = fmaf(s, v.z, acc.z);
            acc.w = fmaf(s, v.w, acc.w);
        }
        const size_t o = (size_t)b * H4 + h;
        ov[o] = acc;
        if (dup) ov[(size_t)B * H4 + o] = acc;
    }
}

// ---------------------------------------------------------------------------
extern "C" void kernel_launch(void* const* d_in, const int* in_sizes, int n_in,
                              void* d_out, int out_size) {
    // metadata order: x[B,H] f32, expert_ids[B,K] i32, expert_scales[B,K] f32,
    //                 golden_expand_x[B*K,H] f32, moe_expert_num i32
    const int*   ids    = (const int*)  d_in[1];
    const float* scales = (const float*)d_in[2];
    const float* G      = (const float*)d_in[3];
    float*       out    = (float*)d_out;

    const int N  = in_sizes[1];                     // B*K = 32768
    const long long GH = (long long)in_sizes[3];    // N*H
    const int H  = (int)(GH / N);                   // 4096
    const int B  = in_sizes[0] / H;                 // 4096
    const int K  = N / B;                           // 8
    const int H4 = H >> 2;
    const int dup = (out_size >= 2 * B * H) ? 1 : 0;

    rank_fused_kernel<<<1, RTHREADS>>>(ids, N);

    const int threads = (H4 >= 1024) ? 1024 : ((H4 + 31) / 32) * 32;
    combine_kernel<<<B, threads>>>(G, scales, out, B, K, H4, dup);
}

// round 4
// speedup vs baseline: 1.0448x; 1.0448x over previous
#include <cuda_runtime.h>

// ---------------------------------------------------------------------------
// MOE_DISTRIBUTE_CASCADE_GRAPH
//   inv[i]   = stable counting-sort rank of expert_ids.flat[i]   (N = B*K)
//   out[b,h] = sum_k scales[b,k] * G[inv[b*K+k], h]
//   output   = (out, out) concatenated (2*B*H floats)
// ---------------------------------------------------------------------------

#define NBINS   256        // max experts supported (dataset uses 64)
#define RWARPS  32         // warps in the rank block
#define RTHREADS (RWARPS * 32)
#define RREGS   32         // ids preloaded per thread (covers N <= 32768)
#define MAXN    65536      // max B*K supported (dataset uses 32768)

__device__ int g_inv[MAXN];

// --- Kernel 1: fused stable counting-sort rank (single block, NO atomics) ---
// Pass 1 computes warp-local stable ranks via __match_any_sync; the leader
// lane does a plain SMEM read-modify-write per distinct key (~2k SMEM ops
// total vs 32768 atomic lane-ops in R2/R3 -> removes the ~65k-cycle ATOMS
// bottleneck). The final counters ARE the per-warp histogram, so no separate
// histogram phase. Pass 2 adds the scanned global bases to the stored ranks.
__global__ void __launch_bounds__(RTHREADS, 1)
rank_fused_kernel(const int* __restrict__ ids, int n) {
    __shared__ int cnt[RWARPS * NBINS];   // running counters -> bases
    __shared__ int totals[NBINS];
    __shared__ int totals2[NBINS];

    const int tid  = threadIdx.x;
    const int w    = tid >> 5;
    const int lane = tid & 31;
    const int cpw  = (n + RWARPS - 1) / RWARPS;   // elems per warp chunk
    const int beg  = w * cpw;
    const int end  = min(beg + cpw, n);

    // Prefetch ids into registers (independent loads, one DRAM latency)
    int myid[RREGS];
    #pragma unroll
    for (int r = 0; r < RREGS; r++) {
        const int i = beg + r * 32 + lane;
        myid[r] = (i < end) ? ids[i] : -1;
    }

    // zero counters
    for (int i = tid; i < RWARPS * NBINS; i += RTHREADS) cnt[i] = 0;
    __syncthreads();

    int* mycnt = &cnt[w * NBINS];

    // ---- Pass 1: warp-local stable ranks + counts (match-based, no atomics)
    #pragma unroll
    for (int r = 0; r < RREGS; r++) {
        const int  id    = myid[r];
        const bool valid = (id >= 0);
        const int  key   = valid ? id : (NBINS + lane);  // singletons if invalid
        const unsigned mask = __match_any_sync(0xffffffffu, key);
        const int lower  = __popc(mask & ((1u << lane) - 1u));
        const int leader = __ffs(mask) - 1;
        int c0 = 0;
        if (valid && lane == leader) {
            c0 = mycnt[key];
            mycnt[key] = c0 + __popc(mask);
        }
        c0 = __shfl_sync(0xffffffffu, c0, leader);
        if (valid) g_inv[beg + r * 32 + lane] = c0 + lower;  // local rank
        __syncwarp();
    }
    // tail (n > RWARPS*32*RREGS): in-loop loads
    for (int i = beg + RREGS * 32 + lane;
         __any_sync(0xffffffffu, i < end); i += 32) {
        const bool valid = (i < end);
        const int key = valid ? ids[i] : (NBINS + lane);
        const unsigned mask = __match_any_sync(0xffffffffu, key);
        const int lower  = __popc(mask & ((1u << lane) - 1u));
        const int leader = __ffs(mask) - 1;
        int c0 = 0;
        if (valid && lane == leader) {
            c0 = mycnt[key];
            mycnt[key] = c0 + __popc(mask);
        }
        c0 = __shfl_sync(0xffffffffu, c0, leader);
        if (valid) g_inv[i] = c0 + lower;
        __syncwarp();
    }
    __syncthreads();

    // ---- Scan 1: per-expert exclusive scan over the 32 warp rows (in SMEM)
    if (tid < NBINS) {
        int run = 0;
        #pragma unroll
        for (int ww = 0; ww < RWARPS; ww++) {
            const int h = cnt[ww * NBINS + tid];
            cnt[ww * NBINS + tid] = run;
            run += h;
        }
        totals[tid] = run;
    }
    __syncthreads();

    // ---- Scan 2: inclusive Hillis-Steele over expert totals
    #pragma unroll
    for (int d = 1; d < NBINS; d <<= 1) {
        int v = 0;
        if (tid < NBINS) v = (tid >= d) ? totals[tid - d] : 0;
        __syncthreads();
        if (tid < NBINS) totals2[tid] = totals[tid] + v;
        __syncthreads();
        if (tid < NBINS) totals[tid] = totals2[tid];
        __syncthreads();
    }
    if (tid < NBINS) {
        const int base = (tid == 0) ? 0 : totals[tid - 1];
        #pragma unroll
        for (int ww = 0; ww < RWARPS; ww++)
            cnt[ww * NBINS + tid] += base;
    }
    __syncthreads();

    // ---- Pass 2: add global bases to stored local ranks (independent RMWs)
    #pragma unroll
    for (int r = 0; r < RREGS; r++) {
        const int id = myid[r];
        if (id >= 0) {
            const int i = beg + r * 32 + lane;
            g_inv[i] += mycnt[id];
        }
    }
    for (int i = beg + RREGS * 32 + lane; i < end; i += 32)
        g_inv[i] += mycnt[ids[i]];
}

// --- Kernel 2: gather-reduce combine (HBM streaming roofline kernel) --------
// 256-thread blocks, 4 resident/SM (reg-limited) so the per-block head stall
// (waiting on g_inv/scales before the first gather) overlaps across blocks.
// 2-D grid: y = token, x = H chunk. K templated for full unroll.
template <int K>
__global__ void __launch_bounds__(256, 4)
combine_kernel(const float* __restrict__ G,
               const float* __restrict__ scales,
               float* __restrict__ out,
               int B, int H4, int dup) {
    const int b = blockIdx.y;
    const int h = blockIdx.x * 256 + threadIdx.x;
    __shared__ int   rows[K];
    __shared__ float sc[K];
    if (threadIdx.x < K) {
        rows[threadIdx.x] = g_inv[b * K + threadIdx.x];
        sc[threadIdx.x]   = scales[b * K + threadIdx.x];
    }
    __syncthreads();
    if (h >= H4) return;

    const float4* __restrict__ Gv = reinterpret_cast<const float4*>(G);
    float4* __restrict__ ov = reinterpret_cast<float4*>(out);

    float4 acc = make_float4(0.f, 0.f, 0.f, 0.f);
    #pragma unroll
    for (int k = 0; k < K; k++) {
        const float  s = sc[k];
        const float4 v = __ldg(&Gv[(size_t)rows[k] * H4 + h]);
        acc.x = fmaf(s, v.x, acc.x);
        acc.y = fmaf(s, v.y, acc.y);
        acc.z = fmaf(s, v.z, acc.z);
        acc.w = fmaf(s, v.w, acc.w);
    }
    const size_t o = (size_t)b * H4 + h;
    ov[o] = acc;
    if (dup) ov[(size_t)B * H4 + o] = acc;
}

// generic-K fallback
__global__ void __launch_bounds__(256, 4)
combine_kernel_gen(const float* __restrict__ G,
                   const float* __restrict__ scales,
                   float* __restrict__ out,
                   int B, int K, int H4, int dup) {
    const int b = blockIdx.y;
    const int h = blockIdx.x * 256 + threadIdx.x;
    __shared__ int   rows[32];
    __shared__ float sc[32];
    if (threadIdx.x < (unsigned)K) {
        rows[threadIdx.x] = g_inv[b * K + threadIdx.x];
        sc[threadIdx.x]   = scales[b * K + threadIdx.x];
    }
    __syncthreads();
    if (h >= H4) return;

    const float4* __restrict__ Gv = reinterpret_cast<const float4*>(G);
    float4* __restrict__ ov = reinterpret_cast<float4*>(out);

    float4 acc = make_float4(0.f, 0.f, 0.f, 0.f);
    for (int k = 0; k < K; k++) {
        const float  s = sc[k];
        const float4 v = __ldg(&Gv[(size_t)rows[k] * H4 + h]);
        acc.x = fmaf(s, v.x, acc.x);
        acc.y = fmaf(s, v.y, acc.y);
        acc.z = fmaf(s, v.z, acc.z);
        acc.w = fmaf(s, v.w, acc.w);
    }
    const size_t o = (size_t)b * H4 + h;
    ov[o] = acc;
    if (dup) ov[(size_t)B * H4 + o] = acc;
}

// ---------------------------------------------------------------------------
extern "C" void kernel_launch(void* const* d_in, const int* in_sizes, int n_in,
                              void* d_out, int out_size) {
    // metadata order: x[B,H] f32, expert_ids[B,K] i32, expert_scales[B,K] f32,
    //                 golden_expand_x[B*K,H] f32, moe_expert_num i32
    const int*   ids    = (const int*)  d_in[1];
    const float* scales = (const float*)d_in[2];
    const float* G      = (const float*)d_in[3];
    float*       out    = (float*)d_out;

    const int N  = in_sizes[1];                     // B*K = 32768
    const long long GH = (long long)in_sizes[3];    // N*H
    const int H  = (int)(GH / N);                   // 4096
    const int B  = in_sizes[0] / H;                 // 4096
    const int K  = N / B;                           // 8
    const int H4 = H >> 2;
    const int dup = (out_size >= 2 * B * H) ? 1 : 0;

    rank_fused_kernel<<<1, RTHREADS>>>(ids, N);

    const int cpb = (H4 + 255) / 256;               // chunks per token
    dim3 grid(cpb, B);
    if (K == 8)
        combine_kernel<8><<<grid, 256>>>(G, scales, out, B, H4, dup);
    else
        combine_kernel_gen<<<grid, 256>>>(G, scales, out, B, K, H4, dup);
}